// round 16
// baseline (speedup 1.0000x reference)
#include <cuda_runtime.h>
#include <cuda_fp16.h>
#include <cstdint>
#include <cstddef>

#define N_NODES 16384
#define IN_F    128
#define OUT_F   64
#define NV      72      // V row stride (64 feats + pad)
#define BI      128     // rows per CTA
#define BJ      128     // j-tile width
#define PSS     136     // P row stride (halves), conflict-free for ldmatrix
#define JSPLIT  16
#define JTILES  (N_NODES / JSPLIT / BJ)   // 8
#define IBLOCKS (N_NODES / BI)            // 128

#define PS_BYTES (BI * PSS * 2)           // 34816 (single buffer, warp-private rows)
#define VS_BYTES (BJ * NV * 2)            // 18432 (SINGLE buffer now)
#define SMEM_TOTAL (PS_BYTES + VS_BYTES + BI * 16)  // 55296 -> 4 CTAs/SM

// Scratch (device globals: allocation-free rule)
__device__ __align__(16) float  g_Wh[N_NODES * OUT_F];
__device__ __align__(16) __half g_V [N_NODES * NV];
__device__ __align__(16) float4 g_rowc[N_NODES];   // {-fi, e^fi, e^{.02fi}, 0}
__device__ __align__(16) float4 g_colc[N_NODES];   // { fj, e^fj, e^{.02fj}, 0}
__device__ __align__(16) float  g_part[(size_t)JSPLIT * N_NODES * NV];  // 75.5MB

// ---------------------------------------------------------------------------
// Kernel A: Wh = x @ W (fp32) + fp16 V
// ---------------------------------------------------------------------------
__global__ __launch_bounds__(256) void wh_kernel(const float* __restrict__ x,
                                                 const float* __restrict__ w) {
    __shared__ float ws[IN_F * OUT_F];
    int tid = threadIdx.x;
    for (int t = tid; t < IN_F * OUT_F; t += 256) ws[t] = w[t];
    __syncthreads();

    int rl  = tid >> 3;
    int c0  = (tid & 7) * 8;
    int row = blockIdx.x * 32 + rl;

    float acc[8];
#pragma unroll
    for (int j = 0; j < 8; j++) acc[j] = 0.f;

    const float4* xr = (const float4*)(x + (size_t)row * IN_F);
#pragma unroll 8
    for (int q = 0; q < 32; q++) {
        float4 xv = __ldg(&xr[q]);
        int k = q * 4;
#pragma unroll
        for (int j = 0; j < 8; j++) acc[j] = fmaf(xv.x, ws[(k + 0) * OUT_F + c0 + j], acc[j]);
#pragma unroll
        for (int j = 0; j < 8; j++) acc[j] = fmaf(xv.y, ws[(k + 1) * OUT_F + c0 + j], acc[j]);
#pragma unroll
        for (int j = 0; j < 8; j++) acc[j] = fmaf(xv.z, ws[(k + 2) * OUT_F + c0 + j], acc[j]);
#pragma unroll
        for (int j = 0; j < 8; j++) acc[j] = fmaf(xv.w, ws[(k + 3) * OUT_F + c0 + j], acc[j]);
    }
#pragma unroll
    for (int j = 0; j < 8; j++) {
        g_Wh[(size_t)row * OUT_F + c0 + j] = acc[j];
        g_V[(size_t)row * NV + c0 + j]     = __float2half(acc[j]);
    }
    if ((tid & 7) == 0) {
#pragma unroll
        for (int t = 64; t < NV; t++) g_V[(size_t)row * NV + t] = __float2half(0.0f);
    }
}

// ---------------------------------------------------------------------------
// Kernel B: attention scalars + exp tables
// ---------------------------------------------------------------------------
__global__ __launch_bounds__(256) void f_kernel(const float* __restrict__ aw) {
    int r = blockIdx.x * blockDim.x + threadIdx.x;
    const float4* whr = (const float4*)(g_Wh + (size_t)r * OUT_F);
    float fi = 0.f, fj = 0.f;
#pragma unroll
    for (int q = 0; q < 16; q++) {
        float4 v = whr[q];
        fi += v.x * __ldg(&aw[q * 4 + 0]) + v.y * __ldg(&aw[q * 4 + 1])
            + v.z * __ldg(&aw[q * 4 + 2]) + v.w * __ldg(&aw[q * 4 + 3]);
        fj += v.x * __ldg(&aw[64 + q * 4 + 0]) + v.y * __ldg(&aw[64 + q * 4 + 1])
            + v.z * __ldg(&aw[64 + q * 4 + 2]) + v.w * __ldg(&aw[64 + q * 4 + 3]);
    }
    g_rowc[r] = make_float4(-fi, expf(fi), expf(0.02f * fi), 0.f);
    g_colc[r] = make_float4(fj,  expf(fj), expf(0.02f * fj), 0.f);
}

// ---------------------------------------------------------------------------
// Main fused kernel: 4 CTAs/SM (32 warps/SM, 8/SMSP). Warp-private P rows,
// SINGLE V buffer with two barriers per tile; register-free L2 prefetch of
// next tile's adj. MMA loads B per-group to keep live regs under the 64 cap.
// ---------------------------------------------------------------------------
__global__ __launch_bounds__(256, 4) void gat_main(const int* __restrict__ adj) {
    extern __shared__ __align__(16) char sm[];
    __half* Ps = (__half*)sm;
    __half* Vs = (__half*)(sm + PS_BYTES);
    float4* rowc = (float4*)(sm + PS_BYTES + VS_BYTES);

    int tid  = threadIdx.x;
    int lane = tid & 31;
    int warp = tid >> 5;
    int i0    = blockIdx.x * BI;
    int jbase = blockIdx.y * (N_NODES / JSPLIT);

    if (tid < BI) rowc[tid] = g_rowc[i0 + tid];

    float c[8][4];
#pragma unroll
    for (int ng = 0; ng < 8; ng++)
#pragma unroll
        for (int q = 0; q < 4; q++) c[ng][q] = 0.f;
    float d0 = 0.f, d1 = 0.f;   // softmax denominator accumulators

    uint32_t ps_u = (uint32_t)__cvta_generic_to_shared(Ps);
    uint32_t vs_u = (uint32_t)__cvta_generic_to_shared(Vs);
    int m0 = warp * 16;                       // warp-private P rows
    uint32_t a_off = 2u * ((m0 + (lane & 15)) * PSS + (lane >> 4) * 8);

    // ---- prologue: prefetch tile-0 adj lines to L2 ----
    {
        const int* pf = adj + (size_t)(i0 + m0) * N_NODES + jbase + 4 * lane;
#pragma unroll
        for (int r = 0; r < 16; r++)
            asm volatile("prefetch.global.L2 [%0];" :: "l"(pf + (size_t)r * N_NODES));
    }

#pragma unroll 1
    for (int t = 0; t < JTILES; t++) {
        int j0 = jbase + t * BJ;

        __syncthreads();   // all MMA(t-1) done: V overwrite safe (also rowc@t=0)

        // ---- V tile (single buffer; g_V is L2-resident) ----
        {
            const uint4* vsrc = (const uint4*)(g_V + (size_t)j0 * NV);
            uint4* vdst = (uint4*)Vs;
#pragma unroll
            for (int q = 0; q < 5; q++) {
                int idx = tid + q * 256;
                if (idx < (BJ * NV) / 8) vdst[idx] = vsrc[idx];
            }
        }

        // ---- P tile, warp-private rows m0..m0+15, lane cols 4*lane.. ----
        const int* adjp = adj + (size_t)(i0 + m0) * N_NODES + j0 + 4 * lane;
        float4 Cc0 = __ldg(&g_colc[j0 + 4 * lane + 0]);
        float4 Cc1 = __ldg(&g_colc[j0 + 4 * lane + 1]);
        float4 Cc2 = __ldg(&g_colc[j0 + 4 * lane + 2]);
        float4 Cc3 = __ldg(&g_colc[j0 + 4 * lane + 3]);

#pragma unroll
        for (int b = 0; b < 4; b++) {
            int4 av[4];
#pragma unroll
            for (int u = 0; u < 4; u++)
                av[u] = __ldg((const int4*)(adjp + (size_t)(b * 4 + u) * N_NODES));
#pragma unroll
            for (int u = 0; u < 4; u++) {
                int r = b * 4 + u;
                float4 R = rowc[m0 + r];          // broadcast LDS.128
                bool s0 = Cc0.x > R.x;            // fj > -fi
                bool s1 = Cc1.x > R.x;
                bool s2 = Cc2.x > R.x;
                bool s3 = Cc3.x > R.x;
                float v0 = (s0 ? R.y : R.z) * (s0 ? Cc0.y : Cc0.z);
                float v1 = (s1 ? R.y : R.z) * (s1 ? Cc1.y : Cc1.z);
                float v2 = (s2 ? R.y : R.z) * (s2 ? Cc2.y : Cc2.z);
                float v3 = (s3 ? R.y : R.z) * (s3 ? Cc3.y : Cc3.z);
                v0 = av[u].x > 0 ? v0 : 0.f;
                v1 = av[u].y > 0 ? v1 : 0.f;
                v2 = av[u].z > 0 ? v2 : 0.f;
                v3 = av[u].w > 0 ? v3 : 0.f;
                __half2 h01 = __floats2half2_rn(v0, v1);
                __half2 h23 = __floats2half2_rn(v2, v3);
                *(uint2*)&Ps[(m0 + r) * PSS + 4 * lane] =
                    make_uint2(*(uint32_t*)&h01, *(uint32_t*)&h23);
            }
        }

        __syncthreads();   // V(t) complete for all warps (and own P visible)

        // ---- register-free L2 prefetch of NEXT tile's adj lines ----
        if (t + 1 < JTILES) {
            const int* pf = adjp + BJ;
#pragma unroll
            for (int r = 0; r < 16; r++)
                asm volatile("prefetch.global.L2 [%0];" :: "l"(pf + (size_t)r * N_NODES));
        }

        // ---- MMA(t): own P rows + V; B loaded per-group (low live regs) ----
        uint32_t abase = ps_u + a_off;
#pragma unroll
        for (int kk = 0; kk < 8; kk++) {
            uint32_t A[4];
            asm volatile("ldmatrix.sync.aligned.m8n8.x4.shared.b16 {%0,%1,%2,%3}, [%4];"
                         : "=r"(A[0]), "=r"(A[1]), "=r"(A[2]), "=r"(A[3])
                         : "r"(abase + kk * 32));
            {   // denominator from A fragments (fma pipe)
                float2 u0 = __half22float2(*(__half2*)&A[0]);
                float2 u2 = __half22float2(*(__half2*)&A[2]);
                float2 u1 = __half22float2(*(__half2*)&A[1]);
                float2 u3 = __half22float2(*(__half2*)&A[3]);
                d0 += (u0.x + u0.y) + (u2.x + u2.y);
                d1 += (u1.x + u1.y) + (u3.x + u3.y);
            }
            uint32_t brow = vs_u + 2u * ((kk * 16 + (lane & 15)) * NV) + ((lane >> 4) << 4);
#pragma unroll
            for (int gp = 0; gp < 4; gp++) {
                uint32_t B0[2], B1[2];
                asm volatile("ldmatrix.sync.aligned.m8n8.x4.trans.shared.b16 {%0,%1,%2,%3}, [%4];"
                             : "=r"(B0[0]), "=r"(B0[1]), "=r"(B1[0]), "=r"(B1[1])
                             : "r"(brow + gp * 32));
                asm volatile("mma.sync.aligned.m16n8k16.row.col.f32.f16.f16.f32 "
                             "{%0,%1,%2,%3}, {%4,%5,%6,%7}, {%8,%9}, {%0,%1,%2,%3};"
                             : "+f"(c[2 * gp][0]), "+f"(c[2 * gp][1]),
                               "+f"(c[2 * gp][2]), "+f"(c[2 * gp][3])
                             : "r"(A[0]), "r"(A[1]), "r"(A[2]), "r"(A[3]),
                               "r"(B0[0]), "r"(B0[1]));
                asm volatile("mma.sync.aligned.m16n8k16.row.col.f32.f16.f16.f32 "
                             "{%0,%1,%2,%3}, {%4,%5,%6,%7}, {%8,%9}, {%0,%1,%2,%3};"
                             : "+f"(c[2 * gp + 1][0]), "+f"(c[2 * gp + 1][1]),
                               "+f"(c[2 * gp + 1][2]), "+f"(c[2 * gp + 1][3])
                             : "r"(A[0]), "r"(A[1]), "r"(A[2]), "r"(A[3]),
                               "r"(B1[0]), "r"(B1[1]));
            }
        }
    }

    // ---- reduce denominators across the 4 lanes of each row group ----
    d0 += __shfl_xor_sync(0xffffffffu, d0, 1);
    d0 += __shfl_xor_sync(0xffffffffu, d0, 2);
    d1 += __shfl_xor_sync(0xffffffffu, d1, 1);
    d1 += __shfl_xor_sync(0xffffffffu, d1, 2);

    // ---- store partials (numerator cols 0..63, denom col 64) ----
    float* pp = g_part + ((size_t)blockIdx.y * N_NODES + i0) * NV;
    int r0 = m0 + (lane >> 2);
    int cb = (lane & 3) * 2;
#pragma unroll
    for (int ng = 0; ng < 8; ng++) {
        *(float2*)&pp[(size_t)r0 * NV + ng * 8 + cb]       = make_float2(c[ng][0], c[ng][1]);
        *(float2*)&pp[(size_t)(r0 + 8) * NV + ng * 8 + cb] = make_float2(c[ng][2], c[ng][3]);
    }
    if ((lane & 3) == 0) {
        pp[(size_t)r0 * NV + 64]       = d0;
        pp[(size_t)(r0 + 8) * NV + 64] = d1;
    }
}

// ---------------------------------------------------------------------------
// Reduce: sum 16 split-partials, divide by denom (col 64), ELU, store.
// ---------------------------------------------------------------------------
__global__ __launch_bounds__(128) void reduce_kernel(float* __restrict__ out) {
    int tid = threadIdx.x;
    int row = blockIdx.x * 4 + (tid >> 5);
    int cp  = tid & 31;

    size_t base = (size_t)row * NV;
    float denom = 0.f, n0 = 0.f, n1 = 0.f;
#pragma unroll
    for (int s = 0; s < JSPLIT; s++) {
        const float* p = g_part + (size_t)s * N_NODES * NV + base;
        denom += __ldg(&p[64]);
        float2 v = *(const float2*)(p + 2 * cp);
        n0 += v.x;
        n1 += v.y;
    }
    float inv = 1.0f / denom;
    float h0 = n0 * inv, h1 = n1 * inv;
    h0 = h0 > 0.f ? h0 : expm1f(h0);
    h1 = h1 > 0.f ? h1 : expm1f(h1);
    *(float2*)&out[(size_t)row * OUT_F + 2 * cp] = make_float2(h0, h1);
}

// ---------------------------------------------------------------------------
extern "C" void kernel_launch(void* const* d_in, const int* in_sizes, int n_in,
                              void* d_out, int out_size) {
    const float* x   = (const float*)d_in[0];   // [16384, 128] f32
    const int*   adj = (const int*)d_in[1];     // [16384, 16384] i32
    const float* w   = (const float*)d_in[2];   // [128, 64] f32
    const float* aw  = (const float*)d_in[3];   // [128, 1] f32
    float* out = (float*)d_out;                 // [16384, 64] f32

    cudaFuncSetAttribute(gat_main, cudaFuncAttributeMaxDynamicSharedMemorySize,
                         SMEM_TOTAL);

    wh_kernel<<<N_NODES / 32, 256>>>(x, w);
    f_kernel<<<N_NODES / 256, 256>>>(aw);
    gat_main<<<dim3(IBLOCKS, JSPLIT), 256, SMEM_TOTAL>>>(adj);
    reduce_kernel<<<N_NODES / 4, 128>>>(out);
}

// round 17
// speedup vs baseline: 1.4363x; 1.4363x over previous
#include <cuda_runtime.h>
#include <cuda_fp16.h>
#include <cstdint>
#include <cstddef>

#define N_NODES 16384
#define IN_F    128
#define OUT_F   64
#define NV      72      // V row stride (64 feats + pad)
#define BI      128     // rows per CTA
#define BJ      128     // j-tile width
#define PSS     136     // P row stride (halves), conflict-free for ldmatrix
#define JSPLIT  16
#define JTILES  (N_NODES / JSPLIT / BJ)   // 8
#define IBLOCKS (N_NODES / BI)            // 128

#define PS_BYTES (BI * PSS * 2)           // 34816 (single buffer, warp-private rows)
#define VS_BYTES (BJ * NV * 2)            // 18432 (double buffered)
#define SMEM_TOTAL (PS_BYTES + 2 * VS_BYTES + BI * 16)  // 73728 -> 3 CTAs/SM

// Scratch (device globals: allocation-free rule)
__device__ __align__(16) __half g_V [N_NODES * NV];
__device__ __align__(16) float4 g_rowc[N_NODES];   // {-fi, e^fi, e^{.02fi}, 0}
__device__ __align__(16) float4 g_colc[N_NODES];   // { fj, e^fj, e^{.02fj}, 0}
__device__ __align__(16) float  g_part[(size_t)JSPLIT * N_NODES * NV];  // 75.5MB

// ---------------------------------------------------------------------------
// Kernel A (fused): Wh = x @ W -> fp16 V, plus per-row attention scalars
// fi = Wh.aw[:64], fj = Wh.aw[64:] reduced across the 8-thread row group.
// ---------------------------------------------------------------------------
__global__ __launch_bounds__(256) void wh_kernel(const float* __restrict__ x,
                                                 const float* __restrict__ w,
                                                 const float* __restrict__ aw) {
    __shared__ float ws[IN_F * OUT_F];
    int tid = threadIdx.x;
    for (int t = tid; t < IN_F * OUT_F; t += 256) ws[t] = w[t];
    __syncthreads();

    int rl  = tid >> 3;
    int c0  = (tid & 7) * 8;
    int row = blockIdx.x * 32 + rl;

    float acc[8];
#pragma unroll
    for (int j = 0; j < 8; j++) acc[j] = 0.f;

    const float4* xr = (const float4*)(x + (size_t)row * IN_F);
#pragma unroll 8
    for (int q = 0; q < 32; q++) {
        float4 xv = __ldg(&xr[q]);
        int k = q * 4;
#pragma unroll
        for (int j = 0; j < 8; j++) acc[j] = fmaf(xv.x, ws[(k + 0) * OUT_F + c0 + j], acc[j]);
#pragma unroll
        for (int j = 0; j < 8; j++) acc[j] = fmaf(xv.y, ws[(k + 1) * OUT_F + c0 + j], acc[j]);
#pragma unroll
        for (int j = 0; j < 8; j++) acc[j] = fmaf(xv.z, ws[(k + 2) * OUT_F + c0 + j], acc[j]);
#pragma unroll
        for (int j = 0; j < 8; j++) acc[j] = fmaf(xv.w, ws[(k + 3) * OUT_F + c0 + j], acc[j]);
    }
#pragma unroll
    for (int j = 0; j < 8; j++)
        g_V[(size_t)row * NV + c0 + j] = __float2half(acc[j]);
    if ((tid & 7) == 0) {
#pragma unroll
        for (int t = 64; t < NV; t++) g_V[(size_t)row * NV + t] = __float2half(0.0f);
    }

    // ---- fused f_i / f_j: partial dots then 8-lane group reduce ----
    float fi = 0.f, fj = 0.f;
#pragma unroll
    for (int j = 0; j < 8; j++) {
        fi = fmaf(acc[j], __ldg(&aw[c0 + j]), fi);
        fj = fmaf(acc[j], __ldg(&aw[64 + c0 + j]), fj);
    }
    // rows occupy 8 consecutive lanes (8-aligned within a warp)
#pragma unroll
    for (int m = 1; m < 8; m <<= 1) {
        fi += __shfl_xor_sync(0xffffffffu, fi, m);
        fj += __shfl_xor_sync(0xffffffffu, fj, m);
    }
    if ((tid & 7) == 0) {
        g_rowc[row] = make_float4(-fi, expf(fi), expf(0.02f * fi), 0.f);
        g_colc[row] = make_float4(fj,  expf(fj), expf(0.02f * fj), 0.f);
    }
}

// ---------------------------------------------------------------------------
// Main fused kernel (R15, unchanged): warp-private P rows, double-buffered V
// with one barrier per tile, register-free L2 prefetch of next tile's adj.
// 256 threads, 3 CTAs/SM -> 6 warps/SMSP.
// ---------------------------------------------------------------------------
__global__ __launch_bounds__(256, 3) void gat_main(const int* __restrict__ adj) {
    extern __shared__ __align__(16) char sm[];
    __half* Ps = (__half*)sm;
    __half* Vs = (__half*)(sm + PS_BYTES);
    float4* rowc = (float4*)(sm + PS_BYTES + 2 * VS_BYTES);

    int tid  = threadIdx.x;
    int lane = tid & 31;
    int warp = tid >> 5;
    int i0    = blockIdx.x * BI;
    int jbase = blockIdx.y * (N_NODES / JSPLIT);

    if (tid < BI) rowc[tid] = g_rowc[i0 + tid];

    float c[8][4];
#pragma unroll
    for (int ng = 0; ng < 8; ng++)
#pragma unroll
        for (int q = 0; q < 4; q++) c[ng][q] = 0.f;
    float d0 = 0.f, d1 = 0.f;   // softmax denominator accumulators

    uint32_t ps_u = (uint32_t)__cvta_generic_to_shared(Ps);
    uint32_t vs_u = (uint32_t)__cvta_generic_to_shared(Vs);
    int m0 = warp * 16;                       // warp-private P rows
    uint32_t a_off = 2u * ((m0 + (lane & 15)) * PSS + (lane >> 4) * 8);

    // ---- prologue: V(0) into buf0 + prefetch tile-0 adj lines to L2 ----
    {
        const uint4* vsrc = (const uint4*)(g_V + (size_t)jbase * NV);
        uint4* vdst = (uint4*)Vs;
#pragma unroll
        for (int q = 0; q < 5; q++) {
            int idx = tid + q * 256;
            if (idx < (BJ * NV) / 8) vdst[idx] = vsrc[idx];
        }
        const int* pf = adj + (size_t)(i0 + m0) * N_NODES + jbase + 4 * lane;
#pragma unroll
        for (int r = 0; r < 16; r++)
            asm volatile("prefetch.global.L2 [%0];" :: "l"(pf + (size_t)r * N_NODES));
    }

#pragma unroll 1
    for (int t = 0; t < JTILES; t++) {
        int j0 = jbase + t * BJ;

        __syncthreads();   // V(t) visible; all warps done reading V(t-1)

        // ---- prefetch V(t+1) into the other buffer ----
        if (t + 1 < JTILES) {
            const uint4* vsrc = (const uint4*)(g_V + (size_t)(j0 + BJ) * NV);
            uint4* vdst = (uint4*)(Vs + ((t + 1) & 1) * (BJ * NV));
#pragma unroll
            for (int q = 0; q < 5; q++) {
                int idx = tid + q * 256;
                if (idx < (BJ * NV) / 8) vdst[idx] = vsrc[idx];
            }
        }

        // ---- P tile, warp-private rows m0..m0+15, lane cols 4*lane.. ----
        const int* adjp = adj + (size_t)(i0 + m0) * N_NODES + j0 + 4 * lane;
        float4 Cc0 = __ldg(&g_colc[j0 + 4 * lane + 0]);
        float4 Cc1 = __ldg(&g_colc[j0 + 4 * lane + 1]);
        float4 Cc2 = __ldg(&g_colc[j0 + 4 * lane + 2]);
        float4 Cc3 = __ldg(&g_colc[j0 + 4 * lane + 3]);

#pragma unroll
        for (int b = 0; b < 4; b++) {
            int4 av[4];
#pragma unroll
            for (int u = 0; u < 4; u++)
                av[u] = __ldg((const int4*)(adjp + (size_t)(b * 4 + u) * N_NODES));
#pragma unroll
            for (int u = 0; u < 4; u++) {
                int r = b * 4 + u;
                float4 R = rowc[m0 + r];          // broadcast LDS.128
                bool s0 = Cc0.x > R.x;            // fj > -fi
                bool s1 = Cc1.x > R.x;
                bool s2 = Cc2.x > R.x;
                bool s3 = Cc3.x > R.x;
                float v0 = (s0 ? R.y : R.z) * (s0 ? Cc0.y : Cc0.z);
                float v1 = (s1 ? R.y : R.z) * (s1 ? Cc1.y : Cc1.z);
                float v2 = (s2 ? R.y : R.z) * (s2 ? Cc2.y : Cc2.z);
                float v3 = (s3 ? R.y : R.z) * (s3 ? Cc3.y : Cc3.z);
                v0 = av[u].x > 0 ? v0 : 0.f;
                v1 = av[u].y > 0 ? v1 : 0.f;
                v2 = av[u].z > 0 ? v2 : 0.f;
                v3 = av[u].w > 0 ? v3 : 0.f;
                __half2 h01 = __floats2half2_rn(v0, v1);
                __half2 h23 = __floats2half2_rn(v2, v3);
                *(uint2*)&Ps[(m0 + r) * PSS + 4 * lane] =
                    make_uint2(*(uint32_t*)&h01, *(uint32_t*)&h23);
            }
        }
        __syncwarp();      // own-warp STS -> LDSM visibility; no CTA barrier

        // ---- register-free L2 prefetch of NEXT tile's adj lines ----
        if (t + 1 < JTILES) {
            const int* pf = adjp + BJ;
#pragma unroll
            for (int r = 0; r < 16; r++)
                asm volatile("prefetch.global.L2 [%0];" :: "l"(pf + (size_t)r * N_NODES));
        }

        // ---- MMA(t): own P rows + V(t); prefetches land underneath ----
        uint32_t vbase = vs_u + (t & 1) * VS_BYTES;
        uint32_t abase = ps_u + a_off;
#pragma unroll
        for (int kk = 0; kk < 8; kk++) {
            uint32_t A[4];
            asm volatile("ldmatrix.sync.aligned.m8n8.x4.shared.b16 {%0,%1,%2,%3}, [%4];"
                         : "=r"(A[0]), "=r"(A[1]), "=r"(A[2]), "=r"(A[3])
                         : "r"(abase + kk * 32));
            {   // denominator from A fragments (fma pipe)
                float2 u0 = __half22float2(*(__half2*)&A[0]);
                float2 u2 = __half22float2(*(__half2*)&A[2]);
                float2 u1 = __half22float2(*(__half2*)&A[1]);
                float2 u3 = __half22float2(*(__half2*)&A[3]);
                d0 += (u0.x + u0.y) + (u2.x + u2.y);
                d1 += (u1.x + u1.y) + (u3.x + u3.y);
            }
            uint32_t B[8][2];
            uint32_t brow = vbase + 2u * ((kk * 16 + (lane & 15)) * NV) + ((lane >> 4) << 4);
#pragma unroll
            for (int gp = 0; gp < 4; gp++) {
                asm volatile("ldmatrix.sync.aligned.m8n8.x4.trans.shared.b16 {%0,%1,%2,%3}, [%4];"
                             : "=r"(B[2 * gp][0]), "=r"(B[2 * gp][1]),
                               "=r"(B[2 * gp + 1][0]), "=r"(B[2 * gp + 1][1])
                             : "r"(brow + gp * 32));
            }
#pragma unroll
            for (int ng = 0; ng < 8; ng++)
                asm volatile("mma.sync.aligned.m16n8k16.row.col.f32.f16.f16.f32 "
                             "{%0,%1,%2,%3}, {%4,%5,%6,%7}, {%8,%9}, {%0,%1,%2,%3};"
                             : "+f"(c[ng][0]), "+f"(c[ng][1]), "+f"(c[ng][2]), "+f"(c[ng][3])
                             : "r"(A[0]), "r"(A[1]), "r"(A[2]), "r"(A[3]),
                               "r"(B[ng][0]), "r"(B[ng][1]));
        }
    }

    // ---- reduce denominators across the 4 lanes of each row group ----
    d0 += __shfl_xor_sync(0xffffffffu, d0, 1);
    d0 += __shfl_xor_sync(0xffffffffu, d0, 2);
    d1 += __shfl_xor_sync(0xffffffffu, d1, 1);
    d1 += __shfl_xor_sync(0xffffffffu, d1, 2);

    // ---- store partials (numerator cols 0..63, denom col 64) ----
    float* pp = g_part + ((size_t)blockIdx.y * N_NODES + i0) * NV;
    int r0 = m0 + (lane >> 2);
    int cb = (lane & 3) * 2;
#pragma unroll
    for (int ng = 0; ng < 8; ng++) {
        *(float2*)&pp[(size_t)r0 * NV + ng * 8 + cb]       = make_float2(c[ng][0], c[ng][1]);
        *(float2*)&pp[(size_t)(r0 + 8) * NV + ng * 8 + cb] = make_float2(c[ng][2], c[ng][3]);
    }
    if ((lane & 3) == 0) {
        pp[(size_t)r0 * NV + 64]       = d0;
        pp[(size_t)(r0 + 8) * NV + 64] = d1;
    }
}

// ---------------------------------------------------------------------------
// Reduce: sum 16 split-partials, divide by denom (col 64), ELU, store.
// ---------------------------------------------------------------------------
__global__ __launch_bounds__(128) void reduce_kernel(float* __restrict__ out) {
    int tid = threadIdx.x;
    int row = blockIdx.x * 4 + (tid >> 5);
    int cp  = tid & 31;

    size_t base = (size_t)row * NV;
    float denom = 0.f, n0 = 0.f, n1 = 0.f;
#pragma unroll
    for (int s = 0; s < JSPLIT; s++) {
        const float* p = g_part + (size_t)s * N_NODES * NV + base;
        denom += __ldg(&p[64]);
        float2 v = *(const float2*)(p + 2 * cp);
        n0 += v.x;
        n1 += v.y;
    }
    float inv = 1.0f / denom;
    float h0 = n0 * inv, h1 = n1 * inv;
    h0 = h0 > 0.f ? h0 : expm1f(h0);
    h1 = h1 > 0.f ? h1 : expm1f(h1);
    *(float2*)&out[(size_t)row * OUT_F + 2 * cp] = make_float2(h0, h1);
}

// ---------------------------------------------------------------------------
extern "C" void kernel_launch(void* const* d_in, const int* in_sizes, int n_in,
                              void* d_out, int out_size) {
    const float* x   = (const float*)d_in[0];   // [16384, 128] f32
    const int*   adj = (const int*)d_in[1];     // [16384, 16384] i32
    const float* w   = (const float*)d_in[2];   // [128, 64] f32
    const float* aw  = (const float*)d_in[3];   // [128, 1] f32
    float* out = (float*)d_out;                 // [16384, 64] f32

    cudaFuncSetAttribute(gat_main, cudaFuncAttributeMaxDynamicSharedMemorySize,
                         SMEM_TOTAL);

    wh_kernel<<<N_NODES / 32, 256>>>(x, w, aw);
    gat_main<<<dim3(IBLOCKS, JSPLIT), 256, SMEM_TOTAL>>>(adj);
    reduce_kernel<<<N_NODES / 4, 128>>>(out);
}